// round 17
// baseline (speedup 1.0000x reference)
#include <cuda_runtime.h>
#include <cuda_bf16.h>

// Persistent-CTA + double-buffered bulk drain.
// 1184 resident CTAs (148 SMs x 8) grid-stride over 256-elem tiles. Two 6KB
// staging buffers per CTA: while buffer p's cp.async.bulk store is in flight,
// the CTA computes the next tile into buffer p^1. The per-tile wait is
// wait_group 1 (normally already satisfied) instead of R13's full wait_group 0
// stall, and CTA launch count drops 15625 -> 1184. Load path identical to the
// proven best (3x LDG.32 + 1x LDG.128, MLP=4).

constexpr int TPB  = 256;
constexpr int GRID = 148 * 8;

__global__ __launch_bounds__(TPB)
void gaussian_cov_kernel(const float* __restrict__ scaling,
                         const float4* __restrict__ rot,
                         float* __restrict__ out,
                         int n)
{
    __shared__ alignas(128) float s_out[2][6 * TPB];  // 2 x 6 KB staged output

    int tid    = threadIdx.x;
    int ntiles = (n + TPB - 1) / TPB;
    int p      = 0;

    for (int tile = blockIdx.x; tile < ntiles; tile += gridDim.x, p ^= 1) {
        int  i    = tile * TPB + tid;
        bool full = (tile + 1) * TPB <= n;  // uniform per tile

        float c00, c01, c02, c11, c12, c22;
        if (i < n) {
            // ---- proven direct load path (MLP=4): 3x LDG.32 + 1x LDG.128 ----
            float a0 = scaling[3 * i + 0];
            float a1 = scaling[3 * i + 1];
            float a2 = scaling[3 * i + 2];
            float4 q = rot[i];

            // s^2 = exp(2*raw): squaring folded into exponent
            float s0 = __expf(a0 + a0);
            float s1 = __expf(a1 + a1);
            float s2 = __expf(a2 + a2);

            float inv = rsqrtf(q.x * q.x + q.y * q.y + q.z * q.z + q.w * q.w);
            float w = q.x * inv, x = q.y * inv, y = q.z * inv, z = q.w * inv;

            float r00 = 1.0f - 2.0f * (y * y + z * z);
            float r01 = 2.0f * (x * y - w * z);
            float r02 = 2.0f * (x * z + w * y);
            float r10 = 2.0f * (x * y + w * z);
            float r11 = 1.0f - 2.0f * (x * x + z * z);
            float r12 = 2.0f * (y * z - w * x);
            float r20 = 2.0f * (x * z - w * y);
            float r21 = 2.0f * (y * z + w * x);
            float r22 = 1.0f - 2.0f * (x * x + y * y);

            c00 = r00 * r00 * s0 + r01 * r01 * s1 + r02 * r02 * s2;
            c01 = r00 * r10 * s0 + r01 * r11 * s1 + r02 * r12 * s2;
            c02 = r00 * r20 * s0 + r01 * r21 * s1 + r02 * r22 * s2;
            c11 = r10 * r10 * s0 + r11 * r11 * s1 + r12 * r12 * s2;
            c12 = r10 * r20 * s0 + r11 * r21 * s1 + r12 * r22 * s2;
            c22 = r20 * r20 * s0 + r21 * r21 * s1 + r22 * r22 * s2;
        }

        // Buffer p's previous bulk store (issued 2 iterations ago) must have
        // completed before we overwrite it. wait_group 1 allows the most
        // recent (other buffer's) store to remain in flight.
        if (tid == 0)
            asm volatile("cp.async.bulk.wait_group 1;" ::: "memory");
        __syncthreads();

        if (i < n) {
            if (full) {
                s_out[p][6 * tid + 0] = c00;
                s_out[p][6 * tid + 1] = c01;
                s_out[p][6 * tid + 2] = c02;
                s_out[p][6 * tid + 3] = c11;
                s_out[p][6 * tid + 4] = c12;
                s_out[p][6 * tid + 5] = c22;
            } else {
                // tail tile: direct scalar stores (not hit for N=4M)
                out[6 * i + 0] = c00; out[6 * i + 1] = c01; out[6 * i + 2] = c02;
                out[6 * i + 3] = c11; out[6 * i + 4] = c12; out[6 * i + 5] = c22;
            }
        }
        __syncthreads();

        if (full && tid == 0) {
            // smem generic-proxy writes must be visible to the async proxy
            asm volatile("fence.proxy.async.shared::cta;" ::: "memory");

            unsigned int smem_addr;
            asm("{ .reg .u64 t; cvta.to.shared.u64 t, %1; cvt.u32.u64 %0, t; }"
                : "=r"(smem_addr) : "l"(&s_out[p][0]));
            float* gp = out + (size_t)tile * (6 * TPB);

            // 6KB bulk store via the async/TMA engine; completion deferred
            asm volatile(
                "cp.async.bulk.global.shared::cta.bulk_group [%0], [%1], %2;"
                :: "l"(gp), "r"(smem_addr), "r"((int)(6 * TPB * sizeof(float)))
                : "memory");
            asm volatile("cp.async.bulk.commit_group;" ::: "memory");
        }
    }

    // Drain all outstanding bulk stores before the CTA (and its smem) retires.
    if (tid == 0)
        asm volatile("cp.async.bulk.wait_group 0;" ::: "memory");
}

extern "C" void kernel_launch(void* const* d_in, const int* in_sizes, int n_in,
                              void* d_out, int out_size)
{
    const float*  scaling = (const float*)d_in[0];   // [N,3] float32
    const float4* rot     = (const float4*)d_in[1];  // [N,4] float32
    float*        out     = (float*)d_out;           // [N,6] float32

    int n = in_sizes[0] / 3;  // N
    int ntiles = (n + TPB - 1) / TPB;
    int blocks = ntiles < GRID ? ntiles : GRID;
    gaussian_cov_kernel<<<blocks, TPB>>>(scaling, rot, out, n);
}